// round 10
// baseline (speedup 1.0000x reference)
#include <cuda_runtime.h>
#include <cuda_bf16.h>
#include <cstdint>

// Problem dims
#define B_   1024
#define T_   256
#define D_   64
#define U_   512
#define HS   (B_*U_)
#define NG   2048          // 4*U_ gate columns (n' = 4u+g interleaved)
#define K1   (D_ + U_)     // 576
#define K2   (2*U_)        // 1024
#define KT1  (K1/32)       // 18 k-tiles per split segment
#define KT2  (K2/32)       // 32

#define NT   512
#define NBLK 128
#define RP   40            // padded smem row stride (bf16) = 80B; ldmatrix conflict-free
#define STAGES 4
#define APITCH (128*RP*2)          // 10240 B, one 128x32 bf16 tile (padded)
#define STAGE_B (2*APITCH)         // A + B per stage
#define SMEM_DYN (STAGES*STAGE_B)  // 81920 B

// ---------------- device globals (no allocations allowed) ----------------
__device__ __align__(16) __nv_bfloat16 g_B1h[NG*K1], g_B1l[NG*K1];
__device__ __align__(16) __nv_bfloat16 g_B2h[NG*K2], g_B2l[NG*K2];
__device__ __align__(16) __nv_bfloat16 g_xh[T_*B_*D_], g_xl[T_*B_*D_];
__device__ __align__(16) __nv_bfloat16 g_h1h[2*HS], g_h1l[2*HS];
__device__ __align__(16) __nv_bfloat16 g_h2h[2*HS], g_h2l[2*HS];
__device__ __align__(16) float g_c1[HS], g_c2[HS], g_h2f[HS];

// Software grid barrier (monotonic generation; reset each replay)
__device__ unsigned g_count;
__device__ volatile unsigned g_gen;

__device__ __forceinline__ void grid_sync(unsigned gen)
{
    __syncthreads();
    if (threadIdx.x == 0) {
        __threadfence();
        unsigned prev = atomicAdd(&g_count, 1u);
        if (prev == gen * NBLK - 1u) {
            __threadfence();
            g_gen = gen;
        } else {
            while (g_gen < gen) { }
            __threadfence();
        }
    }
    __syncthreads();
}

__device__ __forceinline__ float sigmoidf_(float x) { return 1.0f / (1.0f + __expf(-x)); }
__device__ __forceinline__ float tanhf_(float x) {
    float y; asm("tanh.approx.f32 %0, %1;" : "=f"(y) : "f"(x)); return y;
}
__device__ __forceinline__ uint32_t smem_u32(const void* p) {
    return (uint32_t)__cvta_generic_to_shared(p);
}

#define LDSM4(r0, r1, r2, r3, addr) \
    asm volatile("ldmatrix.sync.aligned.m8n8.x4.shared.b16 {%0,%1,%2,%3}, [%4];" \
        : "=r"(r0), "=r"(r1), "=r"(r2), "=r"(r3) : "r"(addr))

#define MMA16816(c, a, b0_, b1_) \
    asm volatile("mma.sync.aligned.m16n8k16.row.col.f32.bf16.bf16.f32 " \
        "{%0,%1,%2,%3}, {%4,%5,%6,%7}, {%8,%9}, {%0,%1,%2,%3};" \
        : "+f"((c)[0]), "+f"((c)[1]), "+f"((c)[2]), "+f"((c)[3]) \
        : "r"((a)[0]), "r"((a)[1]), "r"((a)[2]), "r"((a)[3]), "r"(b0_), "r"(b1_))

#define CP16(sm, gp) \
    asm volatile("cp.async.cg.shared.global [%0], [%1], 16;" :: "r"(sm), "l"(gp))
#define CP_COMMIT() asm volatile("cp.async.commit_group;" ::: "memory")
#define CP_WAIT2()  asm volatile("cp.async.wait_group 2;" ::: "memory")

// ---------------- one layer-step (GEMM over 3 bf16-split segments + cell) ----
__device__ __forceinline__ void layer_step(
    int ktiles, int s0_len,
    const __nv_bfloat16* __restrict__ a0h, const __nv_bfloat16* __restrict__ a0l,
    const __nv_bfloat16* __restrict__ a1h, const __nv_bfloat16* __restrict__ a1l,
    const __nv_bfloat16* __restrict__ Bh,  const __nv_bfloat16* __restrict__ Bl, int Krow,
    const float* __restrict__ bias, float* __restrict__ cst,
    __nv_bfloat16* __restrict__ outh, __nv_bfloat16* __restrict__ outl,
    float* __restrict__ h2f,
    int m0, int n0, int u0, int tid, uint32_t sbase)
{
    const int lane = tid & 31;
    const int ww   = tid >> 5;
    const int wm   = ww & 3;          // m group (32 rows)
    const int wn   = ww >> 2;         // n group (32 n' cols)
    const int n_tiles = 3 * ktiles;
    const int s0_stride = (s0_len == D_) ? D_ : U_;

    float acc[2][4][4];
    #pragma unroll
    for (int i = 0; i < 2; i++)
        #pragma unroll
        for (int j = 0; j < 4; j++)
            #pragma unroll
            for (int q = 0; q < 4; q++) acc[i][j][q] = 0.f;

    // ldmatrix source offsets (bytes)
    const uint32_t aoff = ((wm * 32 + (lane & 15)) * RP + ((lane >> 4) << 3)) * 2;
    const uint32_t boff = ((wn * 32 + (lane & 15)) * RP + ((lane >> 4) << 3)) * 2;

    // cp.async mapping: each thread loads one 16B A chunk + one 16B B chunk
    const int lrow = tid >> 2;        // 0..127
    const int kseg = tid & 3;         // 8-elem segment within k-tile of 32
    const uint32_t s_off = (lrow * RP + kseg * 8) * 2;

    auto issue_load = [&](int tile) {
        const int stage = tile & (STAGES - 1);
        const int seg = (tile >= ktiles) + (tile >= 2 * ktiles);
        const int kb  = (tile - seg * ktiles) * 32;
        const int k   = kb + kseg * 8;
        const bool hi = (seg < 2);
        const __nv_bfloat16* Bs = (seg == 1) ? Bl : Bh;
        const __nv_bfloat16* As; size_t ao;
        if (k < s0_len) { As = hi ? a0h : a0l; ao = (size_t)(m0 + lrow) * s0_stride + k; }
        else            { As = hi ? a1h : a1l; ao = (size_t)(m0 + lrow) * U_ + (k - s0_len); }
        const uint32_t sb = sbase + stage * STAGE_B;
        CP16(sb + s_off, As + ao);
        CP16(sb + APITCH + s_off, Bs + (size_t)(n0 + lrow) * Krow + kb + kseg * 8);
    };

    auto compute = [&](int stage) {
        const uint32_t sa = sbase + stage * STAGE_B + aoff;
        const uint32_t sb = sbase + stage * STAGE_B + APITCH + boff;
        #pragma unroll
        for (int kk = 0; kk < 32; kk += 16) {
            uint32_t a[2][4], b[2][4];
            #pragma unroll
            for (int mf = 0; mf < 2; mf++)
                LDSM4(a[mf][0], a[mf][1], a[mf][2], a[mf][3],
                      sa + (mf * 16 * RP + kk) * 2);
            #pragma unroll
            for (int nb = 0; nb < 2; nb++)
                LDSM4(b[nb][0], b[nb][1], b[nb][2], b[nb][3],
                      sb + (nb * 16 * RP + kk) * 2);
            #pragma unroll
            for (int mf = 0; mf < 2; mf++)
                #pragma unroll
                for (int nb = 0; nb < 2; nb++) {
                    MMA16816(acc[mf][2 * nb],     a[mf], b[nb][0], b[nb][2]);
                    MMA16816(acc[mf][2 * nb + 1], a[mf], b[nb][1], b[nb][3]);
                }
        }
    };

    // prologue: stages 0..2
    #pragma unroll
    for (int s = 0; s < STAGES - 1; s++) { issue_load(s); CP_COMMIT(); }
    CP_WAIT2();
    __syncthreads();

    for (int t = 0; t < n_tiles; t++) {
        if (t + STAGES - 1 < n_tiles) issue_load(t + STAGES - 1);
        CP_COMMIT();                 // uniform group count (empty groups legal)
        compute(t & (STAGES - 1));
        CP_WAIT2();                  // tile t+1 resident
        __syncthreads();             // all warps done with slot overwritten next iter
    }

    // Epilogue: pair lanes (lane^1) to assemble all 4 gates of a unit.
    #pragma unroll
    for (int mf = 0; mf < 2; mf++) {
        const int rbase = m0 + wm * 32 + mf * 16 + (lane >> 2) + 8 * (lane & 1);
        #pragma unroll
        for (int nf = 0; nf < 4; nf++) {
            float c0 = acc[mf][nf][0], c1 = acc[mf][nf][1];
            float c2 = acc[mf][nf][2], c3 = acc[mf][nf][3];
            float p0 = __shfl_xor_sync(0xffffffffu, c0, 1);
            float p1 = __shfl_xor_sync(0xffffffffu, c1, 1);
            float p2 = __shfl_xor_sync(0xffffffffu, c2, 1);
            float p3 = __shfl_xor_sync(0xffffffffu, c3, 1);
            float zi, zf, zg, zo;
            if ((lane & 1) == 0) { zi = c0; zf = c1; zg = p0; zo = p1; }
            else                 { zi = p2; zf = p3; zg = c2; zo = c3; }
            const int u = u0 + wn * 8 + nf * 2 + ((lane & 3) >> 1);
            zi += bias[u];
            zf += bias[U_ + u];
            zg += bias[2 * U_ + u];
            zo += bias[3 * U_ + u];
            const size_t gi = (size_t)rbase * U_ + u;
            const float cold = cst[gi];
            const float cn = sigmoidf_(zf) * cold + sigmoidf_(zi) * tanhf_(zg);
            const float hv = sigmoidf_(zo) * tanhf_(cn);
            cst[gi] = cn;
            const __nv_bfloat16 hh = __float2bfloat16(hv);
            outh[gi] = hh;
            outl[gi] = __float2bfloat16(hv - __bfloat162float(hh));
            if (h2f) h2f[gi] = hv;
        }
    }
}

// ---------------- persistent kernel: 256 steps x 2 layers + dense head ------
__global__ __launch_bounds__(NT, 1)
void lstm_persistent(const float* __restrict__ b1, const float* __restrict__ b2,
                     const float* __restrict__ Wd, const float* __restrict__ bd,
                     float* __restrict__ out)
{
    extern __shared__ char smem[];
    const uint32_t sbase = smem_u32(smem);

    const int tid = threadIdx.x;
    const int n0  = (blockIdx.x & 15) * 128;
    const int m0  = (blockIdx.x >> 4) * 128;
    const int u0  = (blockIdx.x & 15) * 32;

    unsigned gen = 0;
    for (int t = 0; t < T_; t++) {
        const int cur = t & 1;
        layer_step(KT1, D_,
                   g_xh + (size_t)t * (B_ * D_), g_xl + (size_t)t * (B_ * D_),
                   g_h1h + (size_t)cur * HS, g_h1l + (size_t)cur * HS,
                   g_B1h, g_B1l, K1, b1, g_c1,
                   g_h1h + (size_t)(cur ^ 1) * HS, g_h1l + (size_t)(cur ^ 1) * HS,
                   nullptr, m0, n0, u0, tid, sbase);
        grid_sync(++gen);
        layer_step(KT2, U_,
                   g_h1h + (size_t)(cur ^ 1) * HS, g_h1l + (size_t)(cur ^ 1) * HS,
                   g_h2h + (size_t)cur * HS, g_h2l + (size_t)cur * HS,
                   g_B2h, g_B2l, K2, b2, g_c2,
                   g_h2h + (size_t)(cur ^ 1) * HS, g_h2l + (size_t)(cur ^ 1) * HS,
                   g_h2f, m0, n0, u0, tid, sbase);
        grid_sync(++gen);
    }

    // Dense head: 2048 warps; first 1024 take one batch row each.
    const int w = blockIdx.x * (NT / 32) + (tid >> 5);
    const int lane = tid & 31;
    if (w < B_) {
        const float* h = g_h2f + (size_t)w * U_;
        float s = 0.f;
        #pragma unroll
        for (int k = lane; k < U_; k += 32) s += h[k] * Wd[k];
        #pragma unroll
        for (int off = 16; off; off >>= 1) s += __shfl_down_sync(0xffffffffu, s, off);
        if (lane == 0) out[w] = s + bd[0];
    }
}

// ---------------- prep kernels (deterministic, run every replay) ------------
__global__ void prep_weights(const float* __restrict__ W1, const float* __restrict__ Uh1,
                             const float* __restrict__ W2, const float* __restrict__ Uh2)
{
    const long total1 = (long)NG * K1;
    const long total  = total1 + (long)NG * K2;
    for (long idx = blockIdx.x * (long)blockDim.x + threadIdx.x; idx < total;
         idx += (long)gridDim.x * blockDim.x) {
        if (idx < total1) {
            const int np = (int)(idx / K1), k = (int)(idx % K1);
            const int n = ((np & 3) << 9) | (np >> 2);
            const float v = (k < D_) ? W1[(size_t)k * NG + n] : Uh1[(size_t)(k - D_) * NG + n];
            const __nv_bfloat16 hi = __float2bfloat16(v);
            g_B1h[idx] = hi;
            g_B1l[idx] = __float2bfloat16(v - __bfloat162float(hi));
        } else {
            const long i2 = idx - total1;
            const int np = (int)(i2 / K2), k = (int)(i2 % K2);
            const int n = ((np & 3) << 9) | (np >> 2);
            const float v = (k < U_) ? W2[(size_t)k * NG + n] : Uh2[(size_t)(k - U_) * NG + n];
            const __nv_bfloat16 hi = __float2bfloat16(v);
            g_B2h[i2] = hi;
            g_B2l[i2] = __float2bfloat16(v - __bfloat162float(hi));
        }
    }
}

__global__ void prep_x(const float* __restrict__ inputs)
{
    const long total = (long)T_ * B_ * D_;
    for (long idx = blockIdx.x * (long)blockDim.x + threadIdx.x; idx < total;
         idx += (long)gridDim.x * blockDim.x) {
        const int k = (int)(idx & 63);
        const int m = (int)((idx >> 6) & 1023);
        const int t = (int)(idx >> 16);
        const float v = inputs[(size_t)m * (T_ * D_) + (size_t)t * D_ + k];
        const __nv_bfloat16 hi = __float2bfloat16(v);
        g_xh[idx] = hi;
        g_xl[idx] = __float2bfloat16(v - __bfloat162float(hi));
    }
}

__global__ void init_state()
{
    const int i = blockIdx.x * blockDim.x + threadIdx.x;   // HS threads
    const __nv_bfloat16 z = __float2bfloat16(0.f);
    g_h1h[i] = z; g_h1l[i] = z;      // buffer 0
    g_h2h[i] = z; g_h2l[i] = z;
    g_c1[i] = 0.f; g_c2[i] = 0.f;
    if (i == 0) { g_count = 0; g_gen = 0; }
}

extern "C" void kernel_launch(void* const* d_in, const int* in_sizes, int n_in,
                              void* d_out, int out_size)
{
    const float* inputs = (const float*)d_in[0];
    const float* W1  = (const float*)d_in[1];
    const float* Uh1 = (const float*)d_in[2];
    const float* b1  = (const float*)d_in[3];
    const float* W2  = (const float*)d_in[4];
    const float* Uh2 = (const float*)d_in[5];
    const float* b2  = (const float*)d_in[6];
    const float* Wd  = (const float*)d_in[7];
    const float* bd  = (const float*)d_in[8];
    float* out = (float*)d_out;

    cudaFuncSetAttribute(lstm_persistent,
                         cudaFuncAttributeMaxDynamicSharedMemorySize, SMEM_DYN);

    prep_weights<<<2048, 256>>>(W1, Uh1, W2, Uh2);
    prep_x<<<4096, 256>>>(inputs);
    init_state<<<HS / 256, 256>>>();
    lstm_persistent<<<NBLK, NT, SMEM_DYN>>>(b1, b2, Wd, bd, out);
}

// round 11
// speedup vs baseline: 1.3747x; 1.3747x over previous
#include <cuda_runtime.h>
#include <cuda_bf16.h>
#include <cstdint>

// Problem dims
#define B_   1024
#define T_   256
#define D_   64
#define U_   512
#define HS   (B_*U_)
#define NG   2048          // 4*U_ gate columns (n' = 4u+g interleaved)
#define K1   (D_ + U_)     // 576
#define K2   (2*U_)        // 1024

#define NT   512
#define NBLK 128
#define CH   64                       // k per chunk
#define NCH1 (K1/CH)                  // 9  (1 x-chunk + 8 h1-chunks)
#define NCH2 (K2/CH)                  // 16 (8 h1-chunks + 8 h2-chunks)
#define TILEB    16384                // 128 rows x 128B (one 128x64 bf16 tile)
#define STAGE_B  (4*TILEB)            // Ah, Al, Bh, Bl = 64KB
#define STAGES   3
#define SM_TILES 1024                 // mbars live in [0, 24)
#define SMEM_DYN (SM_TILES + STAGES*STAGE_B)   // 197632 B

// A-chunk (h/x): [chunk][1024 m][64] = 65536 elems/chunk, 128B swizzled rows
#define ACH_E 65536
// B-chunk (weights): [chunk][2048 n'][64] = 131072 elems/chunk
#define BCH_E 131072

// ---------------- device globals (no allocations allowed) ----------------
__device__ __align__(16) __nv_bfloat16 g_B1h[NG*K1], g_B1l[NG*K1];
__device__ __align__(16) __nv_bfloat16 g_B2h[NG*K2], g_B2l[NG*K2];
__device__ __align__(16) __nv_bfloat16 g_xh[T_*B_*D_], g_xl[T_*B_*D_];   // [t][m][64] sw
__device__ __align__(16) __nv_bfloat16 g_h1h[2*HS], g_h1l[2*HS];         // [buf][8ch][m][64] sw
__device__ __align__(16) __nv_bfloat16 g_h2h[2*HS], g_h2l[2*HS];
__device__ __align__(16) float g_c1[HS], g_c2[HS], g_h2f[HS];

// Software grid barrier (monotonic generation; reset each replay)
__device__ unsigned g_count;
__device__ volatile unsigned g_gen;

__device__ __forceinline__ void grid_sync(unsigned gen)
{
    __syncthreads();
    if (threadIdx.x == 0) {
        __threadfence();
        unsigned prev = atomicAdd(&g_count, 1u);
        if (prev == gen * NBLK - 1u) {
            __threadfence();
            g_gen = gen;
        } else {
            while (g_gen < gen) { }
            __threadfence();
        }
    }
    __syncthreads();
}

__device__ __host__ __forceinline__ uint32_t SWZb(uint32_t o) { return o ^ ((o >> 3) & 0x70); }

__device__ __forceinline__ float sigmoidf_(float x) { return 1.0f / (1.0f + __expf(-x)); }
__device__ __forceinline__ float tanhf_(float x) {
    float y; asm("tanh.approx.f32 %0, %1;" : "=f"(y) : "f"(x)); return y;
}
__device__ __forceinline__ uint32_t smem_u32(const void* p) {
    return (uint32_t)__cvta_generic_to_shared(p);
}

#define LDSM4(r0, r1, r2, r3, addr) \
    asm volatile("ldmatrix.sync.aligned.m8n8.x4.shared.b16 {%0,%1,%2,%3}, [%4];" \
        : "=r"(r0), "=r"(r1), "=r"(r2), "=r"(r3) : "r"(addr))

#define MMA16816(c, a, b0_, b1_) \
    asm volatile("mma.sync.aligned.m16n8k16.row.col.f32.bf16.bf16.f32 " \
        "{%0,%1,%2,%3}, {%4,%5,%6,%7}, {%8,%9}, {%0,%1,%2,%3};" \
        : "+f"((c)[0]), "+f"((c)[1]), "+f"((c)[2]), "+f"((c)[3]) \
        : "r"((a)[0]), "r"((a)[1]), "r"((a)[2]), "r"((a)[3]), "r"(b0_), "r"(b1_))

#define MBAR_INIT(m, cnt) \
    asm volatile("mbarrier.init.shared.b64 [%0], %1;" :: "r"(m), "r"(cnt) : "memory")
#define MBAR_EXPECT_TX(m, bytes) \
    asm volatile("mbarrier.arrive.expect_tx.shared.b64 _, [%0], %1;" :: "r"(m), "r"(bytes) : "memory")
#define BULK_LD(dst, src, bytes, m) \
    asm volatile("cp.async.bulk.shared::cta.global.mbarrier::complete_tx::bytes [%0], [%1], %2, [%3];" \
        :: "r"(dst), "l"(src), "r"(bytes), "r"(m) : "memory")

__device__ __forceinline__ void mbar_wait(uint32_t m, uint32_t parity)
{
    asm volatile(
        "{\n\t.reg .pred P;\n\t"
        "WL_%=:\n\t"
        "mbarrier.try_wait.parity.acquire.cta.shared::cta.b64 P, [%0], %1, 0x989680;\n\t"
        "@!P bra WL_%=;\n\t}"
        :: "r"(m), "r"(parity) : "memory");
}

// ---------------- one layer-step: bulk-fed GEMM (3 bf16-split products) -----
__device__ __forceinline__ void layer_step(
    int nchunks, int a0_chunks,
    const __nv_bfloat16* __restrict__ a0h, const __nv_bfloat16* __restrict__ a0l,
    const __nv_bfloat16* __restrict__ a1h, const __nv_bfloat16* __restrict__ a1l,
    const __nv_bfloat16* __restrict__ Bh,  const __nv_bfloat16* __restrict__ Bl,
    const float* __restrict__ bias, float* __restrict__ cst,
    __nv_bfloat16* __restrict__ outh, __nv_bfloat16* __restrict__ outl,
    float* __restrict__ h2f,
    int m0, int n0, int u0, int tid, uint32_t sbase)
{
    const int lane = tid & 31;
    const int ww   = tid >> 5;
    const int wm   = ww & 3;          // m group (32 rows)
    const int wn   = ww >> 2;         // n group (32 n' cols)

    // fresh mbarriers each layer_step (all prior uses completed before entry)
    if (tid == 0) {
        MBAR_INIT(sbase + 0, 1);
        MBAR_INIT(sbase + 8, 1);
        MBAR_INIT(sbase + 16, 1);
    }
    __syncthreads();

    float acc[2][4][4];
    #pragma unroll
    for (int i = 0; i < 2; i++)
        #pragma unroll
        for (int j = 0; j < 4; j++)
            #pragma unroll
            for (int q = 0; q < 4; q++) acc[i][j][q] = 0.f;

    auto issue = [&](int c) {     // tid 0 only
        const int s = c % STAGES;
        const uint32_t dst = sbase + SM_TILES + s * STAGE_B;
        const uint32_t mb  = sbase + s * 8;
        const __nv_bfloat16 *Ah, *Al;
        if (c < a0_chunks) { Ah = a0h + (size_t)c * ACH_E; Al = a0l + (size_t)c * ACH_E; }
        else { Ah = a1h + (size_t)(c - a0_chunks) * ACH_E; Al = a1l + (size_t)(c - a0_chunks) * ACH_E; }
        Ah += (size_t)m0 * 64; Al += (size_t)m0 * 64;
        const __nv_bfloat16* bh = Bh + (size_t)c * BCH_E + (size_t)n0 * 64;
        const __nv_bfloat16* bl = Bl + (size_t)c * BCH_E + (size_t)n0 * 64;
        MBAR_EXPECT_TX(mb, (uint32_t)STAGE_B);
        BULK_LD(dst,             Ah, (uint32_t)TILEB, mb);
        BULK_LD(dst + TILEB,     Al, (uint32_t)TILEB, mb);
        BULK_LD(dst + 2*TILEB,   bh, (uint32_t)TILEB, mb);
        BULK_LD(dst + 3*TILEB,   bl, (uint32_t)TILEB, mb);
    };

    auto compute = [&](int s) {
        const uint32_t base = sbase + SM_TILES + s * STAGE_B;
        #pragma unroll
        for (int kk = 0; kk < 64; kk += 16) {
            uint32_t ah[2][4], al[2][4], bh[2][4], bl[2][4];
            #pragma unroll
            for (int mf = 0; mf < 2; mf++) {
                const uint32_t off = SWZb((uint32_t)((wm*32 + mf*16 + (lane & 15)) * 128
                                          + kk * 2 + ((lane >> 4) << 4)));
                LDSM4(ah[mf][0], ah[mf][1], ah[mf][2], ah[mf][3], base + off);
                LDSM4(al[mf][0], al[mf][1], al[mf][2], al[mf][3], base + TILEB + off);
            }
            #pragma unroll
            for (int nb = 0; nb < 2; nb++) {
                const uint32_t off = SWZb((uint32_t)((wn*32 + nb*16 + (lane & 15)) * 128
                                          + kk * 2 + ((lane >> 4) << 4)));
                LDSM4(bh[nb][0], bh[nb][1], bh[nb][2], bh[nb][3], base + 2*TILEB + off);
                LDSM4(bl[nb][0], bl[nb][1], bl[nb][2], bl[nb][3], base + 3*TILEB + off);
            }
            #pragma unroll
            for (int mf = 0; mf < 2; mf++)
                #pragma unroll
                for (int nb = 0; nb < 2; nb++) {
                    // hi*hi
                    MMA16816(acc[mf][2*nb],     ah[mf], bh[nb][0], bh[nb][2]);
                    MMA16816(acc[mf][2*nb + 1], ah[mf], bh[nb][1], bh[nb][3]);
                    // lo*hi
                    MMA16816(acc[mf][2*nb],     al[mf], bh[nb][0], bh[nb][2]);
                    MMA16816(acc[mf][2*nb + 1], al[mf], bh[nb][1], bh[nb][3]);
                    // hi*lo
                    MMA16816(acc[mf][2*nb],     ah[mf], bl[nb][0], bl[nb][2]);
                    MMA16816(acc[mf][2*nb + 1], ah[mf], bl[nb][1], bl[nb][3]);
                }
        }
    };

    if (tid == 0) { issue(0); if (nchunks > 1) issue(1); }
    for (int c = 0; c < nchunks; c++) {
        if (tid == 0 && c + 2 < nchunks) issue(c + 2);
        mbar_wait(sbase + (c % STAGES) * 8, (c / STAGES) & 1);
        compute(c % STAGES);
        __syncthreads();     // all warps done with this stage before it's refilled
    }

    // Epilogue: pair lanes (lane^1) to assemble all 4 gates of a unit.
    #pragma unroll
    for (int mf = 0; mf < 2; mf++) {
        const int rbase = m0 + wm * 32 + mf * 16 + (lane >> 2) + 8 * (lane & 1);
        #pragma unroll
        for (int nf = 0; nf < 4; nf++) {
            float c0 = acc[mf][nf][0], c1 = acc[mf][nf][1];
            float c2 = acc[mf][nf][2], c3 = acc[mf][nf][3];
            float p0 = __shfl_xor_sync(0xffffffffu, c0, 1);
            float p1 = __shfl_xor_sync(0xffffffffu, c1, 1);
            float p2 = __shfl_xor_sync(0xffffffffu, c2, 1);
            float p3 = __shfl_xor_sync(0xffffffffu, c3, 1);
            float zi, zf, zg, zo;
            if ((lane & 1) == 0) { zi = c0; zf = c1; zg = p0; zo = p1; }
            else                 { zi = p2; zf = p3; zg = c2; zo = c3; }
            const int u = u0 + wn * 8 + nf * 2 + ((lane & 3) >> 1);
            zi += bias[u];
            zf += bias[U_ + u];
            zg += bias[2 * U_ + u];
            zo += bias[3 * U_ + u];
            const size_t gi = (size_t)rbase * U_ + u;   // linear index (c, h2f)
            const float cold = cst[gi];
            const float cn = sigmoidf_(zf) * cold + sigmoidf_(zi) * tanhf_(zg);
            const float hv = sigmoidf_(zo) * tanhf_(cn);
            cst[gi] = cn;
            // h in chunked swizzled layout: [u>>6][m][64]
            const uint32_t ho = (uint32_t)(u >> 6) * ACH_E
                              + (SWZb((uint32_t)rbase * 128 + (uint32_t)(u & 63) * 2) >> 1);
            const __nv_bfloat16 hh = __float2bfloat16(hv);
            outh[ho] = hh;
            outl[ho] = __float2bfloat16(hv - __bfloat162float(hh));
            if (h2f) h2f[gi] = hv;
        }
    }
}

// ---------------- persistent kernel: 256 steps x 2 layers + dense head ------
__global__ __launch_bounds__(NT, 1)
void lstm_persistent(const float* __restrict__ b1, const float* __restrict__ b2,
                     const float* __restrict__ Wd, const float* __restrict__ bd,
                     float* __restrict__ out)
{
    extern __shared__ __align__(1024) char smem[];
    const uint32_t sbase = smem_u32(smem);

    const int tid = threadIdx.x;
    const int n0  = (blockIdx.x & 15) * 128;
    const int m0  = (blockIdx.x >> 4) * 128;
    const int u0  = (blockIdx.x & 15) * 32;

    unsigned gen = 0;
    for (int t = 0; t < T_; t++) {
        const int cur = t & 1;
        // layer 1: A = [x_t (1 chunk) | h1_prev (8 chunks)]
        layer_step(NCH1, 1,
                   g_xh + (size_t)t * ACH_E, g_xl + (size_t)t * ACH_E,
                   g_h1h + (size_t)cur * HS, g_h1l + (size_t)cur * HS,
                   g_B1h, g_B1l, b1, g_c1,
                   g_h1h + (size_t)(cur ^ 1) * HS, g_h1l + (size_t)(cur ^ 1) * HS,
                   nullptr, m0, n0, u0, tid, sbase);
        grid_sync(++gen);
        // layer 2: A = [h1_new (8 chunks) | h2_prev (8 chunks)]
        layer_step(NCH2, 8,
                   g_h1h + (size_t)(cur ^ 1) * HS, g_h1l + (size_t)(cur ^ 1) * HS,
                   g_h2h + (size_t)cur * HS, g_h2l + (size_t)cur * HS,
                   g_B2h, g_B2l, b2, g_c2,
                   g_h2h + (size_t)(cur ^ 1) * HS, g_h2l + (size_t)(cur ^ 1) * HS,
                   g_h2f, m0, n0, u0, tid, sbase);
        grid_sync(++gen);
    }

    // Dense head: 2048 warps; first 1024 take one batch row each.
    const int w = blockIdx.x * (NT / 32) + (tid >> 5);
    const int lane = tid & 31;
    if (w < B_) {
        const float* h = g_h2f + (size_t)w * U_;
        float s = 0.f;
        #pragma unroll
        for (int k = lane; k < U_; k += 32) s += h[k] * Wd[k];
        #pragma unroll
        for (int off = 16; off; off >>= 1) s += __shfl_down_sync(0xffffffffu, s, off);
        if (lane == 0) out[w] = s + bd[0];
    }
}

// ---------------- prep kernels (deterministic, run every replay) ------------
// Weights -> [chunk][n'][64], SW128-swizzled 128B rows, hi/lo split.
__global__ void prep_weights(const float* __restrict__ W1, const float* __restrict__ Uh1,
                             const float* __restrict__ W2, const float* __restrict__ Uh2)
{
    const long total1 = (long)NG * K1;
    const long total  = total1 + (long)NG * K2;
    for (long idx = blockIdx.x * (long)blockDim.x + threadIdx.x; idx < total;
         idx += (long)gridDim.x * blockDim.x) {
        if (idx < total1) {
            const int np = (int)(idx / K1), k = (int)(idx % K1);
            const int n = ((np & 3) << 9) | (np >> 2);
            const float v = (k < D_) ? W1[(size_t)k * NG + n] : Uh1[(size_t)(k - D_) * NG + n];
            const __nv_bfloat16 hi = __float2bfloat16(v);
            const long o = (long)(k >> 6) * BCH_E
                         + (SWZb((uint32_t)np * 128 + (uint32_t)(k & 63) * 2) >> 1);
            g_B1h[o] = hi;
            g_B1l[o] = __float2bfloat16(v - __bfloat162float(hi));
        } else {
            const long i2 = idx - total1;
            const int np = (int)(i2 / K2), k = (int)(i2 % K2);
            const int n = ((np & 3) << 9) | (np >> 2);
            const float v = (k < U_) ? W2[(size_t)k * NG + n] : Uh2[(size_t)(k - U_) * NG + n];
            const __nv_bfloat16 hi = __float2bfloat16(v);
            const long o = (long)(k >> 6) * BCH_E
                         + (SWZb((uint32_t)np * 128 + (uint32_t)(k & 63) * 2) >> 1);
            g_B2h[o] = hi;
            g_B2l[o] = __float2bfloat16(v - __bfloat162float(hi));
        }
    }
}

// x -> [t][m][64], SW128-swizzled rows, hi/lo split
__global__ void prep_x(const float* __restrict__ inputs)
{
    const long total = (long)T_ * B_ * D_;
    for (long idx = blockIdx.x * (long)blockDim.x + threadIdx.x; idx < total;
         idx += (long)gridDim.x * blockDim.x) {
        const int k = (int)(idx & 63);
        const int m = (int)((idx >> 6) & 1023);
        const int t = (int)(idx >> 16);
        const float v = inputs[(size_t)m * (T_ * D_) + (size_t)t * D_ + k];
        const __nv_bfloat16 hi = __float2bfloat16(v);
        const long o = (long)t * ACH_E + (SWZb((uint32_t)m * 128 + (uint32_t)k * 2) >> 1);
        g_xh[o] = hi;
        g_xl[o] = __float2bfloat16(v - __bfloat162float(hi));
    }
}

__global__ void init_state()
{
    const int i = blockIdx.x * blockDim.x + threadIdx.x;   // HS threads
    const __nv_bfloat16 z = __float2bfloat16(0.f);
    g_h1h[i] = z; g_h1l[i] = z;      // buffer 0 (initial state; layout-independent zeros)
    g_h2h[i] = z; g_h2l[i] = z;
    g_c1[i] = 0.f; g_c2[i] = 0.f;
    if (i == 0) { g_count = 0; g_gen = 0; }
}

extern "C" void kernel_launch(void* const* d_in, const int* in_sizes, int n_in,
                              void* d_out, int out_size)
{
    const float* inputs = (const float*)d_in[0];
    const float* W1  = (const float*)d_in[1];
    const float* Uh1 = (const float*)d_in[2];
    const float* b1  = (const float*)d_in[3];
    const float* W2  = (const float*)d_in[4];
    const float* Uh2 = (const float*)d_in[5];
    const float* b2  = (const float*)d_in[6];
    const float* Wd  = (const float*)d_in[7];
    const float* bd  = (const float*)d_in[8];
    float* out = (float*)d_out;

    cudaFuncSetAttribute(lstm_persistent,
                         cudaFuncAttributeMaxDynamicSharedMemorySize, SMEM_DYN);

    prep_weights<<<2048, 256>>>(W1, Uh1, W2, Uh2);
    prep_x<<<4096, 256>>>(inputs);
    init_state<<<HS / 256, 256>>>();
    lstm_persistent<<<NBLK, NT, SMEM_DYN>>>(b1, b2, Wd, bd, out);
}

// round 12
// speedup vs baseline: 1.4147x; 1.0291x over previous
#include <cuda_runtime.h>
#include <cuda_bf16.h>
#include <cstdint>

// Problem dims
#define B_   1024
#define T_   256
#define D_   64
#define U_   512
#define HS   (B_*U_)
#define NG   2048          // 4*U_ gate columns (n' = 4u+g interleaved)
#define K1   (D_ + U_)     // 576
#define K2   (2*U_)        // 1024

#define NT   256
#define NBLK 256
#define CH   64                       // k per chunk
#define NCH1 (K1/CH)                  // 9  (1 x-chunk + 8 h1-chunks)
#define NCH2 (K2/CH)                  // 16 (8 h1-chunks + 8 h2-chunks)
#define ATILE_B  8192                 // 64 rows x 128B  (A: 64x64 bf16)
#define BTILE_B  16384                // 128 rows x 128B (B: 128x64 bf16)
#define STAGE_B  (2*ATILE_B + 2*BTILE_B)   // Ah, Al, Bh, Bl = 48KB
#define STAGES   2
#define SM_TILES 1024                 // mbars live in [0, 16)
#define SMEM_DYN (SM_TILES + STAGES*STAGE_B)   // 99328 B -> 2 CTAs/SM

// A-chunk (h/x): [chunk][1024 m][64] = 65536 elems/chunk, 128B swizzled rows
#define ACH_E 65536
// B-chunk (weights): [chunk][2048 n'][64] = 131072 elems/chunk
#define BCH_E 131072

// ---------------- device globals (no allocations allowed) ----------------
__device__ __align__(16) __nv_bfloat16 g_B1h[NG*K1], g_B1l[NG*K1];
__device__ __align__(16) __nv_bfloat16 g_B2h[NG*K2], g_B2l[NG*K2];
__device__ __align__(16) __nv_bfloat16 g_xh[T_*B_*D_], g_xl[T_*B_*D_];   // [t][m][64] sw
__device__ __align__(16) __nv_bfloat16 g_h1h[2*HS], g_h1l[2*HS];         // [buf][8ch][m][64] sw
__device__ __align__(16) __nv_bfloat16 g_h2h[2*HS], g_h2l[2*HS];
__device__ __align__(16) float g_c1[HS], g_c2[HS], g_h2f[HS];

// Software grid barrier (monotonic generation; reset each replay)
__device__ unsigned g_count;
__device__ volatile unsigned g_gen;

__device__ __forceinline__ void grid_sync(unsigned gen)
{
    __syncthreads();
    if (threadIdx.x == 0) {
        __threadfence();
        unsigned prev = atomicAdd(&g_count, 1u);
        if (prev == gen * NBLK - 1u) {
            __threadfence();
            g_gen = gen;
        } else {
            while (g_gen < gen) { }
            __threadfence();
        }
    }
    __syncthreads();
}

__device__ __host__ __forceinline__ uint32_t SWZb(uint32_t o) { return o ^ ((o >> 3) & 0x70); }

__device__ __forceinline__ float sigmoidf_(float x) { return 1.0f / (1.0f + __expf(-x)); }
__device__ __forceinline__ float tanhf_(float x) {
    float y; asm("tanh.approx.f32 %0, %1;" : "=f"(y) : "f"(x)); return y;
}
__device__ __forceinline__ uint32_t smem_u32(const void* p) {
    return (uint32_t)__cvta_generic_to_shared(p);
}

#define LDSM4(r0, r1, r2, r3, addr) \
    asm volatile("ldmatrix.sync.aligned.m8n8.x4.shared.b16 {%0,%1,%2,%3}, [%4];" \
        : "=r"(r0), "=r"(r1), "=r"(r2), "=r"(r3) : "r"(addr))

#define MMA16816(c, a, b0_, b1_) \
    asm volatile("mma.sync.aligned.m16n8k16.row.col.f32.bf16.bf16.f32 " \
        "{%0,%1,%2,%3}, {%4,%5,%6,%7}, {%8,%9}, {%0,%1,%2,%3};" \
        : "+f"((c)[0]), "+f"((c)[1]), "+f"((c)[2]), "+f"((c)[3]) \
        : "r"((a)[0]), "r"((a)[1]), "r"((a)[2]), "r"((a)[3]), "r"(b0_), "r"(b1_))

#define MBAR_INIT(m, cnt) \
    asm volatile("mbarrier.init.shared.b64 [%0], %1;" :: "r"(m), "r"(cnt) : "memory")
#define MBAR_EXPECT_TX(m, bytes) \
    asm volatile("mbarrier.arrive.expect_tx.shared.b64 _, [%0], %1;" :: "r"(m), "r"(bytes) : "memory")
#define BULK_LD(dst, src, bytes, m) \
    asm volatile("cp.async.bulk.shared::cta.global.mbarrier::complete_tx::bytes [%0], [%1], %2, [%3];" \
        :: "r"(dst), "l"(src), "r"(bytes), "r"(m) : "memory")

__device__ __forceinline__ void mbar_wait(uint32_t m, uint32_t parity)
{
    asm volatile(
        "{\n\t.reg .pred P;\n\t"
        "WL_%=:\n\t"
        "mbarrier.try_wait.parity.acquire.cta.shared::cta.b64 P, [%0], %1, 0x989680;\n\t"
        "@!P bra WL_%=;\n\t}"
        :: "r"(m), "r"(parity) : "memory");
}

// ---------------- one layer-step: bulk-fed GEMM (3 bf16-split products) -----
// CTA tile: 64 m-rows x 128 n' (32 units x 4 gates). 8 warps: wm = ww&1, wn = ww>>1.
__device__ __forceinline__ void layer_step(
    int nchunks, int a0_chunks,
    const __nv_bfloat16* __restrict__ a0h, const __nv_bfloat16* __restrict__ a0l,
    const __nv_bfloat16* __restrict__ a1h, const __nv_bfloat16* __restrict__ a1l,
    const __nv_bfloat16* __restrict__ Bh,  const __nv_bfloat16* __restrict__ Bl,
    const float* __restrict__ bias, float* __restrict__ cst,
    __nv_bfloat16* __restrict__ outh, __nv_bfloat16* __restrict__ outl,
    float* __restrict__ h2f,
    int m0, int n0, int u0, int tid, uint32_t sbase)
{
    const int lane = tid & 31;
    const int ww   = tid >> 5;        // 0..7
    const int wm   = ww & 1;          // m group (32 rows)
    const int wn   = ww >> 1;         // n group (32 n' cols)

    // fresh mbarriers each layer_step (all prior uses completed before entry)
    if (tid == 0) {
        MBAR_INIT(sbase + 0, 1);
        MBAR_INIT(sbase + 8, 1);
    }
    __syncthreads();

    float acc[2][4][4];
    #pragma unroll
    for (int i = 0; i < 2; i++)
        #pragma unroll
        for (int j = 0; j < 4; j++)
            #pragma unroll
            for (int q = 0; q < 4; q++) acc[i][j][q] = 0.f;

    auto issue = [&](int c) {     // tid 0 only
        const int s = c & 1;
        const uint32_t dst = sbase + SM_TILES + s * STAGE_B;
        const uint32_t mb  = sbase + s * 8;
        const __nv_bfloat16 *Ah, *Al;
        if (c < a0_chunks) { Ah = a0h + (size_t)c * ACH_E; Al = a0l + (size_t)c * ACH_E; }
        else { Ah = a1h + (size_t)(c - a0_chunks) * ACH_E; Al = a1l + (size_t)(c - a0_chunks) * ACH_E; }
        Ah += (size_t)m0 * 64; Al += (size_t)m0 * 64;
        const __nv_bfloat16* bh = Bh + (size_t)c * BCH_E + (size_t)n0 * 64;
        const __nv_bfloat16* bl = Bl + (size_t)c * BCH_E + (size_t)n0 * 64;
        MBAR_EXPECT_TX(mb, (uint32_t)STAGE_B);
        BULK_LD(dst,                       Ah, (uint32_t)ATILE_B, mb);
        BULK_LD(dst + ATILE_B,             Al, (uint32_t)ATILE_B, mb);
        BULK_LD(dst + 2*ATILE_B,           bh, (uint32_t)BTILE_B, mb);
        BULK_LD(dst + 2*ATILE_B + BTILE_B, bl, (uint32_t)BTILE_B, mb);
    };

    auto compute = [&](int s) {
        const uint32_t base = sbase + SM_TILES + s * STAGE_B;
        #pragma unroll
        for (int kk = 0; kk < 64; kk += 16) {
            uint32_t ah[2][4], al[2][4], bh[2][4], bl[2][4];
            #pragma unroll
            for (int mf = 0; mf < 2; mf++) {
                const uint32_t off = SWZb((uint32_t)((wm*32 + mf*16 + (lane & 15)) * 128
                                          + kk * 2 + ((lane >> 4) << 4)));
                LDSM4(ah[mf][0], ah[mf][1], ah[mf][2], ah[mf][3], base + off);
                LDSM4(al[mf][0], al[mf][1], al[mf][2], al[mf][3], base + ATILE_B + off);
            }
            #pragma unroll
            for (int nb = 0; nb < 2; nb++) {
                const uint32_t off = SWZb((uint32_t)((wn*32 + nb*16 + (lane & 15)) * 128
                                          + kk * 2 + ((lane >> 4) << 4)));
                LDSM4(bh[nb][0], bh[nb][1], bh[nb][2], bh[nb][3], base + 2*ATILE_B + off);
                LDSM4(bl[nb][0], bl[nb][1], bl[nb][2], bl[nb][3], base + 2*ATILE_B + BTILE_B + off);
            }
            #pragma unroll
            for (int mf = 0; mf < 2; mf++)
                #pragma unroll
                for (int nb = 0; nb < 2; nb++) {
                    // hi*hi
                    MMA16816(acc[mf][2*nb],     ah[mf], bh[nb][0], bh[nb][2]);
                    MMA16816(acc[mf][2*nb + 1], ah[mf], bh[nb][1], bh[nb][3]);
                    // lo*hi
                    MMA16816(acc[mf][2*nb],     al[mf], bh[nb][0], bh[nb][2]);
                    MMA16816(acc[mf][2*nb + 1], al[mf], bh[nb][1], bh[nb][3]);
                    // hi*lo
                    MMA16816(acc[mf][2*nb],     ah[mf], bl[nb][0], bl[nb][2]);
                    MMA16816(acc[mf][2*nb + 1], ah[mf], bl[nb][1], bl[nb][3]);
                }
        }
    };

    if (tid == 0) { issue(0); if (nchunks > 1) issue(1); }
    for (int c = 0; c < nchunks; c++) {
        mbar_wait(sbase + (c & 1) * 8, (c >> 1) & 1);
        compute(c & 1);
        __syncthreads();     // all warps done with this stage before refill
        if (tid == 0 && c + 2 < nchunks) issue(c + 2);
    }

    // Epilogue: pair lanes (lane^1) to assemble all 4 gates of a unit.
    #pragma unroll
    for (int mf = 0; mf < 2; mf++) {
        const int rbase = m0 + wm * 32 + mf * 16 + (lane >> 2) + 8 * (lane & 1);
        #pragma unroll
        for (int nf = 0; nf < 4; nf++) {
            float c0 = acc[mf][nf][0], c1 = acc[mf][nf][1];
            float c2 = acc[mf][nf][2], c3 = acc[mf][nf][3];
            float p0 = __shfl_xor_sync(0xffffffffu, c0, 1);
            float p1 = __shfl_xor_sync(0xffffffffu, c1, 1);
            float p2 = __shfl_xor_sync(0xffffffffu, c2, 1);
            float p3 = __shfl_xor_sync(0xffffffffu, c3, 1);
            float zi, zf, zg, zo;
            if ((lane & 1) == 0) { zi = c0; zf = c1; zg = p0; zo = p1; }
            else                 { zi = p2; zf = p3; zg = c2; zo = c3; }
            const int u = u0 + wn * 8 + nf * 2 + ((lane & 3) >> 1);
            zi += bias[u];
            zf += bias[U_ + u];
            zg += bias[2 * U_ + u];
            zo += bias[3 * U_ + u];
            const size_t gi = (size_t)rbase * U_ + u;   // linear index (c, h2f)
            const float cold = cst[gi];
            const float cn = sigmoidf_(zf) * cold + sigmoidf_(zi) * tanhf_(zg);
            const float hv = sigmoidf_(zo) * tanhf_(cn);
            cst[gi] = cn;
            // h in chunked swizzled layout: [u>>6][m][64]
            const uint32_t ho = (uint32_t)(u >> 6) * ACH_E
                              + (SWZb((uint32_t)rbase * 128 + (uint32_t)(u & 63) * 2) >> 1);
            const __nv_bfloat16 hh = __float2bfloat16(hv);
            outh[ho] = hh;
            outl[ho] = __float2bfloat16(hv - __bfloat162float(hh));
            if (h2f) h2f[gi] = hv;
        }
    }
}

// ---------------- persistent kernel: 256 steps x 2 layers + dense head ------
__global__ __launch_bounds__(NT, 2)
void lstm_persistent(const float* __restrict__ b1, const float* __restrict__ b2,
                     const float* __restrict__ Wd, const float* __restrict__ bd,
                     float* __restrict__ out)
{
    extern __shared__ __align__(1024) char smem[];
    const uint32_t sbase = smem_u32(smem);

    const int tid = threadIdx.x;
    const int n0  = (blockIdx.x & 15) * 128;
    const int m0  = (blockIdx.x >> 4) * 64;
    const int u0  = (blockIdx.x & 15) * 32;

    unsigned gen = 0;
    for (int t = 0; t < T_; t++) {
        const int cur = t & 1;
        // layer 1: A = [x_t (1 chunk) | h1_prev (8 chunks)]
        layer_step(NCH1, 1,
                   g_xh + (size_t)t * ACH_E, g_xl + (size_t)t * ACH_E,
                   g_h1h + (size_t)cur * HS, g_h1l + (size_t)cur * HS,
                   g_B1h, g_B1l, b1, g_c1,
                   g_h1h + (size_t)(cur ^ 1) * HS, g_h1l + (size_t)(cur ^ 1) * HS,
                   nullptr, m0, n0, u0, tid, sbase);
        grid_sync(++gen);
        // layer 2: A = [h1_new (8 chunks) | h2_prev (8 chunks)]
        layer_step(NCH2, 8,
                   g_h1h + (size_t)(cur ^ 1) * HS, g_h1l + (size_t)(cur ^ 1) * HS,
                   g_h2h + (size_t)cur * HS, g_h2l + (size_t)cur * HS,
                   g_B2h, g_B2l, b2, g_c2,
                   g_h2h + (size_t)(cur ^ 1) * HS, g_h2l + (size_t)(cur ^ 1) * HS,
                   g_h2f, m0, n0, u0, tid, sbase);
        grid_sync(++gen);
    }

    // Dense head: 256 blocks x 8 warps = 2048 warps; first 1024 take one row.
    const int w = blockIdx.x * (NT / 32) + (tid >> 5);
    const int lane = tid & 31;
    if (w < B_) {
        const float* h = g_h2f + (size_t)w * U_;
        float s = 0.f;
        #pragma unroll
        for (int k = lane; k < U_; k += 32) s += h[k] * Wd[k];
        #pragma unroll
        for (int off = 16; off; off >>= 1) s += __shfl_down_sync(0xffffffffu, s, off);
        if (lane == 0) out[w] = s + bd[0];
    }
}

// ---------------- prep kernels (deterministic, run every replay) ------------
// Weights -> [chunk][n'][64], SW128-swizzled 128B rows, hi/lo split.
__global__ void prep_weights(const float* __restrict__ W1, const float* __restrict__ Uh1,
                             const float* __restrict__ W2, const float* __restrict__ Uh2)
{
    const long total1 = (long)NG * K1;
    const long total  = total1 + (long)NG * K2;
    for (long idx = blockIdx.x * (long)blockDim.x + threadIdx.x; idx < total;
         idx += (long)gridDim.x * blockDim.x) {
        if (idx < total1) {
            const int np = (int)(idx / K1), k = (int)(idx % K1);
            const int n = ((np & 3) << 9) | (np >> 2);
            const float v = (k < D_) ? W1[(size_t)k * NG + n] : Uh1[(size_t)(k - D_) * NG + n];
            const __nv_bfloat16 hi = __float2bfloat16(v);
            const long o = (long)(k >> 6) * BCH_E
                         + (SWZb((uint32_t)np * 128 + (uint32_t)(k & 63) * 2) >> 1);
            g_B1h[o] = hi;
            g_B1l[o] = __float2bfloat16(v - __bfloat162float(hi));
        } else {
            const long i2 = idx - total1;
            const int np = (int)(i2 / K2), k = (int)(i2 % K2);
            const int n = ((np & 3) << 9) | (np >> 2);
            const float v = (k < U_) ? W2[(size_t)k * NG + n] : Uh2[(size_t)(k - U_) * NG + n];
            const __nv_bfloat16 hi = __float2bfloat16(v);
            const long o = (long)(k >> 6) * BCH_E
                         + (SWZb((uint32_t)np * 128 + (uint32_t)(k & 63) * 2) >> 1);
            g_B2h[o] = hi;
            g_B2l[o] = __float2bfloat16(v - __bfloat162float(hi));
        }
    }
}

// x -> [t][m][64], SW128-swizzled rows, hi/lo split
__global__ void prep_x(const float* __restrict__ inputs)
{
    const long total = (long)T_ * B_ * D_;
    for (long idx = blockIdx.x * (long)blockDim.x + threadIdx.x; idx < total;
         idx += (long)gridDim.x * blockDim.x) {
        const int k = (int)(idx & 63);
        const int m = (int)((idx >> 6) & 1023);
        const int t = (int)(idx >> 16);
        const float v = inputs[(size_t)m * (T_ * D_) + (size_t)t * D_ + k];
        const __nv_bfloat16 hi = __float2bfloat16(v);
        const long o = (long)t * ACH_E + (SWZb((uint32_t)m * 128 + (uint32_t)k * 2) >> 1);
        g_xh[o] = hi;
        g_xl[o] = __float2bfloat16(v - __bfloat162float(hi));
    }
}

__global__ void init_state()
{
    const int i = blockIdx.x * blockDim.x + threadIdx.x;   // HS threads
    const __nv_bfloat16 z = __float2bfloat16(0.f);
    g_h1h[i] = z; g_h1l[i] = z;      // buffer 0 (zeros; layout-independent)
    g_h2h[i] = z; g_h2l[i] = z;
    g_c1[i] = 0.f; g_c2[i] = 0.f;
    if (i == 0) { g_count = 0; g_gen = 0; }
}

extern "C" void kernel_launch(void* const* d_in, const int* in_sizes, int n_in,
                              void* d_out, int out_size)
{
    const float* inputs = (const float*)d_in[0];
    const float* W1  = (const float*)d_in[1];
    const float* Uh1 = (const float*)d_in[2];
    const float* b1  = (const float*)d_in[3];
    const float* W2  = (const float*)d_in[4];
    const float* Uh2 = (const float*)d_in[5];
    const float* b2  = (const float*)d_in[6];
    const float* Wd  = (const float*)d_in[7];
    const float* bd  = (const float*)d_in[8];
    float* out = (float*)d_out;

    cudaFuncSetAttribute(lstm_persistent,
                         cudaFuncAttributeMaxDynamicSharedMemorySize, SMEM_DYN);

    prep_weights<<<2048, 256>>>(W1, Uh1, W2, Uh2);
    prep_x<<<4096, 256>>>(inputs);
    init_state<<<HS / 256, 256>>>();
    lstm_persistent<<<NBLK, NT, SMEM_DYN>>>(b1, b2, Wd, bd, out);
}

// round 13
// speedup vs baseline: 2.0212x; 1.4287x over previous
#include <cuda_runtime.h>
#include <cuda_fp16.h>
#include <cstdint>

// Problem dims
#define B_   1024
#define T_   256
#define D_   64
#define U_   512
#define HS   (B_*U_)
#define NG   2048          // 4*U_ gate columns (n' = 4u+g interleaved)
#define K1   (D_ + U_)     // 576
#define K2   (2*U_)        // 1024

#define NT   512
#define NBLK 128
#define NCH1 9                        // 1 x-chunk + 8 h1-chunks (64 k each)
#define NCH2 16                       // 8 h1-chunks + 8 h2-chunks
#define TILE16 16384                  // one 128x64 fp16 tile (128B rows, SW128)
#define STAGE_B  65536                // A0,A1,B0,B1 (up to 2 chunks) = 64KB
#define STAGES   3
#define SM_TILES 1024                 // mbars live in [0, 24)
#define SMEM_DYN (SM_TILES + STAGES*STAGE_B)   // 197632 B (1 CTA/SM)

// A-chunk (h/x): [chunk][1024 m][64] = 65536 elems, swizzled 128B rows
#define ACH_E 65536
// B-chunk (weights): [chunk][2048 n'][64] = 131072 elems
#define BCH_E 131072

// ---------------- device globals (no allocations allowed) ----------------
__device__ __align__(16) __half g_B1[NG*K1], g_B2[NG*K2];
__device__ __align__(16) __half g_xf[T_*B_*D_];            // [t][m][64] sw
__device__ __align__(16) __half g_h1[2*HS], g_h2[2*HS];    // [buf][8ch][m][64] sw
__device__ __align__(16) float g_c1[HS], g_c2[HS], g_h2f[HS];

// Software grid barrier (monotonic generation; reset each replay)
__device__ unsigned g_count;
__device__ volatile unsigned g_gen;

__device__ __forceinline__ void grid_sync(unsigned gen)
{
    __syncthreads();
    if (threadIdx.x == 0) {
        __threadfence();
        unsigned prev = atomicAdd(&g_count, 1u);
        if (prev == gen * NBLK - 1u) {
            __threadfence();
            g_gen = gen;
        } else {
            while (g_gen < gen) { }
            __threadfence();
        }
    }
    __syncthreads();
}

__device__ __host__ __forceinline__ uint32_t SWZb(uint32_t o) { return o ^ ((o >> 3) & 0x70); }

__device__ __forceinline__ float sigmoidf_(float x) { return 1.0f / (1.0f + __expf(-x)); }
__device__ __forceinline__ float tanhf_(float x) {
    float y; asm("tanh.approx.f32 %0, %1;" : "=f"(y) : "f"(x)); return y;
}
__device__ __forceinline__ uint32_t smem_u32(const void* p) {
    return (uint32_t)__cvta_generic_to_shared(p);
}

#define LDSM4(r0, r1, r2, r3, addr) \
    asm volatile("ldmatrix.sync.aligned.m8n8.x4.shared.b16 {%0,%1,%2,%3}, [%4];" \
        : "=r"(r0), "=r"(r1), "=r"(r2), "=r"(r3) : "r"(addr))

#define MMA16816(c, a, b0_, b1_) \
    asm volatile("mma.sync.aligned.m16n8k16.row.col.f32.f16.f16.f32 " \
        "{%0,%1,%2,%3}, {%4,%5,%6,%7}, {%8,%9}, {%0,%1,%2,%3};" \
        : "+f"((c)[0]), "+f"((c)[1]), "+f"((c)[2]), "+f"((c)[3]) \
        : "r"((a)[0]), "r"((a)[1]), "r"((a)[2]), "r"((a)[3]), "r"(b0_), "r"(b1_))

#define MBAR_INIT(m, cnt) \
    asm volatile("mbarrier.init.shared.b64 [%0], %1;" :: "r"(m), "r"(cnt) : "memory")
#define MBAR_EXPECT_TX(m, bytes) \
    asm volatile("mbarrier.arrive.expect_tx.shared.b64 _, [%0], %1;" :: "r"(m), "r"(bytes) : "memory")
#define BULK_LD(dst, src, bytes, m) \
    asm volatile("cp.async.bulk.shared::cta.global.mbarrier::complete_tx::bytes [%0], [%1], %2, [%3];" \
        :: "r"(dst), "l"(src), "r"(bytes), "r"(m) : "memory")

__device__ __forceinline__ void mbar_wait(uint32_t m, uint32_t parity)
{
    asm volatile(
        "{\n\t.reg .pred P;\n\t"
        "WL_%=:\n\t"
        "mbarrier.try_wait.parity.acquire.cta.shared::cta.b64 P, [%0], %1, 0x989680;\n\t"
        "@!P bra WL_%=;\n\t}"
        :: "r"(m), "r"(parity) : "memory");
}

// ---------------- one layer-step: bulk-fed single-fp16 GEMM + cell ----------
// CTA tile: 128 m x 128 n'. 16 warps: wm = ww&3 (32 rows), wn = ww>>2 (32 n').
__device__ __forceinline__ void layer_step(
    int nchunks, int a0_chunks,
    const __half* __restrict__ a0, const __half* __restrict__ a1,
    const __half* __restrict__ Bw,
    const float* __restrict__ bias, float* __restrict__ cst,
    __half* __restrict__ outp, float* __restrict__ h2f,
    int m0, int n0, int u0, int tid, uint32_t sbase)
{
    const int lane = tid & 31;
    const int ww   = tid >> 5;        // 0..15
    const int wm   = ww & 3;
    const int wn   = ww >> 2;

    // stage table: up to 2 chunks/stage, never spanning the a0|a1 boundary
    int spos[8], slen[8], nst = 0;
    for (int pos = 0; pos < nchunks; ) {
        int len = (nchunks - pos < 2) ? (nchunks - pos) : 2;
        if (pos < a0_chunks && pos + len > a0_chunks) len = a0_chunks - pos;
        spos[nst] = pos; slen[nst] = len; nst++; pos += len;
    }

    if (tid == 0) {
        MBAR_INIT(sbase + 0, 1);
        MBAR_INIT(sbase + 8, 1);
        MBAR_INIT(sbase + 16, 1);
    }
    __syncthreads();

    float acc[2][4][4];
    #pragma unroll
    for (int i = 0; i < 2; i++)
        #pragma unroll
        for (int j = 0; j < 4; j++)
            #pragma unroll
            for (int q = 0; q < 4; q++) acc[i][j][q] = 0.f;

    auto issue = [&](int s) {     // tid 0 only
        const int slot = s % STAGES;
        const uint32_t dst = sbase + SM_TILES + slot * STAGE_B;
        const uint32_t mb  = sbase + slot * 8;
        const int pos = spos[s], len = slen[s];
        MBAR_EXPECT_TX(mb, (uint32_t)(len * 2 * TILE16));
        for (int sub = 0; sub < len; sub++) {
            const int c = pos + sub;
            const __half* A = (c < a0_chunks) ? (a0 + (size_t)c * ACH_E)
                                              : (a1 + (size_t)(c - a0_chunks) * ACH_E);
            BULK_LD(dst + sub * TILE16,             A + (size_t)m0 * 64, (uint32_t)TILE16, mb);
            BULK_LD(dst + (2 + sub) * TILE16,
                    Bw + (size_t)c * BCH_E + (size_t)n0 * 64, (uint32_t)TILE16, mb);
        }
    };

    auto compute = [&](int slot, int len) {
        const uint32_t base = sbase + SM_TILES + slot * STAGE_B;
        for (int sub = 0; sub < len; sub++) {
            const uint32_t ab = base + sub * TILE16;
            const uint32_t bb = base + (2 + sub) * TILE16;
            #pragma unroll
            for (int kk = 0; kk < 64; kk += 16) {
                uint32_t a[2][4], b[2][4];
                #pragma unroll
                for (int mf = 0; mf < 2; mf++) {
                    const uint32_t off = SWZb((uint32_t)((wm*32 + mf*16 + (lane & 15)) * 128
                                              + kk * 2 + ((lane >> 4) << 4)));
                    LDSM4(a[mf][0], a[mf][1], a[mf][2], a[mf][3], ab + off);
                }
                #pragma unroll
                for (int nb = 0; nb < 2; nb++) {
                    const uint32_t off = SWZb((uint32_t)((wn*32 + nb*16 + (lane & 15)) * 128
                                              + kk * 2 + ((lane >> 4) << 4)));
                    LDSM4(b[nb][0], b[nb][1], b[nb][2], b[nb][3], bb + off);
                }
                #pragma unroll
                for (int mf = 0; mf < 2; mf++)
                    #pragma unroll
                    for (int nb = 0; nb < 2; nb++) {
                        MMA16816(acc[mf][2*nb],     a[mf], b[nb][0], b[nb][2]);
                        MMA16816(acc[mf][2*nb + 1], a[mf], b[nb][1], b[nb][3]);
                    }
            }
        }
    };

    if (tid == 0) { issue(0); if (nst > 1) issue(1); }
    for (int s = 0; s < nst; s++) {
        if (tid == 0 && s + 2 < nst) issue(s + 2);
        mbar_wait(sbase + (s % STAGES) * 8, (s / STAGES) & 1);
        compute(s % STAGES, slen[s]);
        __syncthreads();     // all warps done with this slot before refill
    }

    // Epilogue: pair lanes (lane^1) to assemble all 4 gates of a unit.
    #pragma unroll
    for (int mf = 0; mf < 2; mf++) {
        const int rbase = m0 + wm * 32 + mf * 16 + (lane >> 2) + 8 * (lane & 1);
        #pragma unroll
        for (int nf = 0; nf < 4; nf++) {
            float c0 = acc[mf][nf][0], c1 = acc[mf][nf][1];
            float c2 = acc[mf][nf][2], c3 = acc[mf][nf][3];
            float p0 = __shfl_xor_sync(0xffffffffu, c0, 1);
            float p1 = __shfl_xor_sync(0xffffffffu, c1, 1);
            float p2 = __shfl_xor_sync(0xffffffffu, c2, 1);
            float p3 = __shfl_xor_sync(0xffffffffu, c3, 1);
            float zi, zf, zg, zo;
            if ((lane & 1) == 0) { zi = c0; zf = c1; zg = p0; zo = p1; }
            else                 { zi = p2; zf = p3; zg = c2; zo = c3; }
            const int u = u0 + wn * 8 + nf * 2 + ((lane & 3) >> 1);
            zi += bias[u];
            zf += bias[U_ + u];
            zg += bias[2 * U_ + u];
            zo += bias[3 * U_ + u];
            const size_t gi = (size_t)rbase * U_ + u;   // linear index (c, h2f)
            const float cold = cst[gi];
            const float cn = sigmoidf_(zf) * cold + sigmoidf_(zi) * tanhf_(zg);
            const float hv = sigmoidf_(zo) * tanhf_(cn);
            cst[gi] = cn;
            // h in chunked swizzled layout: [u>>6][m][64]
            const uint32_t ho = (uint32_t)(u >> 6) * ACH_E
                              + (SWZb((uint32_t)rbase * 128 + (uint32_t)(u & 63) * 2) >> 1);
            outp[ho] = __float2half_rn(hv);
            if (h2f) h2f[gi] = hv;
        }
    }
}

// ---------------- persistent kernel: 256 steps x 2 layers + dense head ------
__global__ __launch_bounds__(NT, 1)
void lstm_persistent(const float* __restrict__ b1, const float* __restrict__ b2,
                     const float* __restrict__ Wd, const float* __restrict__ bd,
                     float* __restrict__ out)
{
    extern __shared__ __align__(1024) char smem[];
    const uint32_t sbase = smem_u32(smem);

    const int tid = threadIdx.x;
    const int n0  = (blockIdx.x & 15) * 128;
    const int m0  = (blockIdx.x >> 4) * 128;
    const int u0  = (blockIdx.x & 15) * 32;

    unsigned gen = 0;
    for (int t = 0; t < T_; t++) {
        const int cur = t & 1;
        // layer 1: A = [x_t (1 chunk) | h1_prev (8 chunks)]
        layer_step(NCH1, 1,
                   g_xf + (size_t)t * ACH_E,
                   g_h1 + (size_t)cur * HS,
                   g_B1, b1, g_c1,
                   g_h1 + (size_t)(cur ^ 1) * HS, nullptr,
                   m0, n0, u0, tid, sbase);
        grid_sync(++gen);
        // layer 2: A = [h1_new (8 chunks) | h2_prev (8 chunks)]
        layer_step(NCH2, 8,
                   g_h1 + (size_t)(cur ^ 1) * HS,
                   g_h2 + (size_t)cur * HS,
                   g_B2, b2, g_c2,
                   g_h2 + (size_t)(cur ^ 1) * HS, g_h2f,
                   m0, n0, u0, tid, sbase);
        grid_sync(++gen);
    }

    // Dense head: 128 blocks x 16 warps = 2048 warps; first 1024 take one row.
    const int w = blockIdx.x * (NT / 32) + (tid >> 5);
    const int lane = tid & 31;
    if (w < B_) {
        const float* h = g_h2f + (size_t)w * U_;
        float s = 0.f;
        #pragma unroll
        for (int k = lane; k < U_; k += 32) s += h[k] * Wd[k];
        #pragma unroll
        for (int off = 16; off; off >>= 1) s += __shfl_down_sync(0xffffffffu, s, off);
        if (lane == 0) out[w] = s + bd[0];
    }
}

// ---------------- prep kernels (deterministic, run every replay) ------------
// Weights -> [chunk][n'][64] fp16, SW128-swizzled 128B rows.
__global__ void prep_weights(const float* __restrict__ W1, const float* __restrict__ Uh1,
                             const float* __restrict__ W2, const float* __restrict__ Uh2)
{
    const long total1 = (long)NG * K1;
    const long total  = total1 + (long)NG * K2;
    for (long idx = blockIdx.x * (long)blockDim.x + threadIdx.x; idx < total;
         idx += (long)gridDim.x * blockDim.x) {
        if (idx < total1) {
            const int np = (int)(idx / K1), k = (int)(idx % K1);
            const int n = ((np & 3) << 9) | (np >> 2);
            const float v = (k < D_) ? W1[(size_t)k * NG + n] : Uh1[(size_t)(k - D_) * NG + n];
            const long o = (long)(k >> 6) * BCH_E
                         + (SWZb((uint32_t)np * 128 + (uint32_t)(k & 63) * 2) >> 1);
            g_B1[o] = __float2half_rn(v);
        } else {
            const long i2 = idx - total1;
            const int np = (int)(i2 / K2), k = (int)(i2 % K2);
            const int n = ((np & 3) << 9) | (np >> 2);
            const float v = (k < U_) ? W2[(size_t)k * NG + n] : Uh2[(size_t)(k - U_) * NG + n];
            const long o = (long)(k >> 6) * BCH_E
                         + (SWZb((uint32_t)np * 128 + (uint32_t)(k & 63) * 2) >> 1);
            g_B2[o] = __float2half_rn(v);
        }
    }
}

// x -> [t][m][64] fp16, SW128-swizzled rows
__global__ void prep_x(const float* __restrict__ inputs)
{
    const long total = (long)T_ * B_ * D_;
    for (long idx = blockIdx.x * (long)blockDim.x + threadIdx.x; idx < total;
         idx += (long)gridDim.x * blockDim.x) {
        const int k = (int)(idx & 63);
        const int m = (int)((idx >> 6) & 1023);
        const int t = (int)(idx >> 16);
        const float v = inputs[(size_t)m * (T_ * D_) + (size_t)t * D_ + k];
        const long o = (long)t * ACH_E + (SWZb((uint32_t)m * 128 + (uint32_t)k * 2) >> 1);
        g_xf[o] = __float2half_rn(v);
    }
}

__global__ void init_state()
{
    const int i = blockIdx.x * blockDim.x + threadIdx.x;   // HS threads
    const __half z = __float2half_rn(0.f);
    g_h1[i] = z;                     // buffer 0 (zeros; layout-independent)
    g_h2[i] = z;
    g_c1[i] = 0.f; g_c2[i] = 0.f;
    if (i == 0) { g_count = 0; g_gen = 0; }
}

extern "C" void kernel_launch(void* const* d_in, const int* in_sizes, int n_in,
                              void* d_out, int out_size)
{
    const float* inputs = (const float*)d_in[0];
    const float* W1  = (const float*)d_in[1];
    const float* Uh1 = (const float*)d_in[2];
    const float* b1  = (const float*)d_in[3];
    const float* W2  = (const float*)d_in[4];
    const float* Uh2 = (const float*)d_in[5];
    const float* b2  = (const float*)d_in[6];
    const float* Wd  = (const float*)d_in[7];
    const float* bd  = (const float*)d_in[8];
    float* out = (float*)d_out;

    cudaFuncSetAttribute(lstm_persistent,
                         cudaFuncAttributeMaxDynamicSharedMemorySize, SMEM_DYN);

    prep_weights<<<2048, 256>>>(W1, Uh1, W2, Uh2);
    prep_x<<<4096, 256>>>(inputs);
    init_state<<<HS / 256, 256>>>();
    lstm_persistent<<<NBLK, NT, SMEM_DYN>>>(b1, b2, Wd, bd, out);
}

// round 14
// speedup vs baseline: 2.6206x; 1.2965x over previous
#include <cuda_runtime.h>
#include <cuda_fp16.h>
#include <cstdint>

// Problem dims
#define B_   1024
#define T_   256
#define D_   64
#define U_   512
#define HS   (B_*U_)
#define NG   2048          // 4*U_ gate columns (n' = 4u+g interleaved)
#define K1   (D_ + U_)     // 576
#define K2   (2*U_)        // 1024

#define NT   512
#define NBLK 128
#define NCH1 9                        // 1 x-chunk + 8 h1-chunks (64 k each)
#define NCH2 16                       // 8 h1-chunks + 8 h2-chunks
#define NSLOT 6                       // pipeline slots (1 chunk each)
#define LA   4                        // producer lookahead (stages)
#define TILE16 16384                  // one 128x64 fp16 tile (128B rows, SW128)
#define STAGE_B 32768                 // A tile + B tile
#define SM_TILES 1024                 // mbars in [0, 96): full[i]@16i, empty[i]@16i+8
#define SMEM_DYN (SM_TILES + NSLOT*STAGE_B)   // 197632 B (1 CTA/SM)

// A-chunk (h/x): [chunk][1024 m][64] = 65536 elems, swizzled 128B rows
#define ACH_E 65536
// B-chunk (weights): [chunk][2048 n'][64] = 131072 elems
#define BCH_E 131072

// ---------------- device globals (no allocations allowed) ----------------
__device__ __align__(16) __half g_B1[NG*K1], g_B2[NG*K2];
__device__ __align__(16) __half g_xf[T_*B_*D_];            // [t][m][64] sw
__device__ __align__(16) __half g_h1[2*HS], g_h2[2*HS];    // [buf][8ch][m][64] sw
__device__ __align__(16) float g_c1[HS], g_c2[HS], g_h2f[HS];

// Software grid barrier (monotonic generation; reset each replay)
__device__ unsigned g_count;
__device__ volatile unsigned g_gen;

__device__ __forceinline__ void grid_sync(unsigned gen)
{
    __syncthreads();
    if (threadIdx.x == 0) {
        __threadfence();
        unsigned prev = atomicAdd(&g_count, 1u);
        if (prev == gen * NBLK - 1u) {
            __threadfence();
            g_gen = gen;
        } else {
            while (g_gen < gen) { }
            __threadfence();
        }
    }
    __syncthreads();
}

__device__ __host__ __forceinline__ uint32_t SWZb(uint32_t o) { return o ^ ((o >> 3) & 0x70); }

__device__ __forceinline__ float sigmoidf_(float x) { return 1.0f / (1.0f + __expf(-x)); }
__device__ __forceinline__ float tanhf_(float x) {
    float y; asm("tanh.approx.f32 %0, %1;" : "=f"(y) : "f"(x)); return y;
}
__device__ __forceinline__ uint32_t smem_u32(const void* p) {
    return (uint32_t)__cvta_generic_to_shared(p);
}

#define LDSM4(r0, r1, r2, r3, addr) \
    asm volatile("ldmatrix.sync.aligned.m8n8.x4.shared.b16 {%0,%1,%2,%3}, [%4];" \
        : "=r"(r0), "=r"(r1), "=r"(r2), "=r"(r3) : "r"(addr))

#define MMA16816(c, a, b0_, b1_) \
    asm volatile("mma.sync.aligned.m16n8k16.row.col.f32.f16.f16.f32 " \
        "{%0,%1,%2,%3}, {%4,%5,%6,%7}, {%8,%9}, {%0,%1,%2,%3};" \
        : "+f"((c)[0]), "+f"((c)[1]), "+f"((c)[2]), "+f"((c)[3]) \
        : "r"((a)[0]), "r"((a)[1]), "r"((a)[2]), "r"((a)[3]), "r"(b0_), "r"(b1_))

#define MBAR_INIT(m, cnt) \
    asm volatile("mbarrier.init.shared.b64 [%0], %1;" :: "r"(m), "r"(cnt) : "memory")
#define MBAR_EXPECT_TX(m, bytes) \
    asm volatile("mbarrier.arrive.expect_tx.shared.b64 _, [%0], %1;" :: "r"(m), "r"(bytes) : "memory")
#define MBAR_ARRIVE(m) \
    asm volatile("mbarrier.arrive.shared.b64 _, [%0];" :: "r"(m) : "memory")
#define BULK_LD(dst, src, bytes, m) \
    asm volatile("cp.async.bulk.shared::cta.global.mbarrier::complete_tx::bytes [%0], [%1], %2, [%3];" \
        :: "r"(dst), "l"(src), "r"(bytes), "r"(m) : "memory")

__device__ __forceinline__ void mbar_wait(uint32_t m, uint32_t parity)
{
    asm volatile(
        "{\n\t.reg .pred P;\n\t"
        "WL_%=:\n\t"
        "mbarrier.try_wait.parity.acquire.cta.shared::cta.b64 P, [%0], %1, 0x989680;\n\t"
        "@!P bra WL_%=;\n\t}"
        :: "r"(m), "r"(parity) : "memory");
}

struct JobP { int nch; int a0n; const __half *a0, *a1, *Bw; };

// ---------------- persistent kernel: fused phases + dense head --------------
__global__ __launch_bounds__(NT, 1)
void lstm_persistent(const float* __restrict__ b1, const float* __restrict__ b2,
                     const float* __restrict__ Wd, const float* __restrict__ bd,
                     float* __restrict__ out)
{
    extern __shared__ __align__(1024) char smem[];
    const uint32_t sbase = smem_u32(smem);

    const int tid  = threadIdx.x;
    const int lane = tid & 31;
    const int ww   = tid >> 5;        // 0..15
    const int wm   = ww & 3;          // m group (32 rows)
    const int wn   = ww >> 2;         // n group (32 n' cols)
    const int n0 = (blockIdx.x & 15) * 128;
    const int m0 = (blockIdx.x >> 4) * 128;
    const int u0 = (blockIdx.x & 15) * 32;

    // persistent mbarriers: full[i] (1 tx-arrive), empty[i] (16 warp-arrives)
    if (tid == 0)
        for (int i = 0; i < NSLOT; i++) {
            MBAR_INIT(sbase + i * 16, 1);
            MBAR_INIT(sbase + i * 16 + 8, 16);
        }
    __syncthreads();

    int pslot = 0, pph = 1;   // producer cursor (waits empty; fresh barrier passes @parity 1)
    int cslot = 0, cph = 0;   // consumer cursor (waits full)

    float acc[2][4][4];
    auto zero_acc = [&] {
        #pragma unroll
        for (int i = 0; i < 2; i++)
            #pragma unroll
            for (int j = 0; j < 4; j++)
                #pragma unroll
                for (int q = 0; q < 4; q++) acc[i][j][q] = 0.f;
    };

    auto issue_one = [&](const __half* A, const __half* Bw) {   // tid 0 only
        mbar_wait(sbase + pslot * 16 + 8, (uint32_t)pph);
        const uint32_t full = sbase + pslot * 16;
        const uint32_t dst  = sbase + SM_TILES + pslot * STAGE_B;
        MBAR_EXPECT_TX(full, (uint32_t)STAGE_B);
        BULK_LD(dst,          A,  (uint32_t)TILE16, full);
        BULK_LD(dst + TILE16, Bw, (uint32_t)TILE16, full);
        if (++pslot == NSLOT) { pslot = 0; pph ^= 1; }
    };

    auto consume_one = [&] {
        mbar_wait(sbase + cslot * 16, (uint32_t)cph);
        const uint32_t ab = sbase + SM_TILES + cslot * STAGE_B;
        const uint32_t bb = ab + TILE16;
        #pragma unroll
        for (int kk = 0; kk < 64; kk += 16) {
            uint32_t a[2][4], b[2][4];
            #pragma unroll
            for (int mf = 0; mf < 2; mf++) {
                const uint32_t off = SWZb((uint32_t)((wm*32 + mf*16 + (lane & 15)) * 128
                                          + kk * 2 + ((lane >> 4) << 4)));
                LDSM4(a[mf][0], a[mf][1], a[mf][2], a[mf][3], ab + off);
            }
            #pragma unroll
            for (int nb = 0; nb < 2; nb++) {
                const uint32_t off = SWZb((uint32_t)((wn*32 + nb*16 + (lane & 15)) * 128
                                          + kk * 2 + ((lane >> 4) << 4)));
                LDSM4(b[nb][0], b[nb][1], b[nb][2], b[nb][3], bb + off);
            }
            #pragma unroll
            for (int mf = 0; mf < 2; mf++)
                #pragma unroll
                for (int nb = 0; nb < 2; nb++) {
                    MMA16816(acc[mf][2*nb],     a[mf], b[nb][0], b[nb][2]);
                    MMA16816(acc[mf][2*nb + 1], a[mf], b[nb][1], b[nb][3]);
                }
        }
        __syncwarp();
        if (lane == 0) MBAR_ARRIVE(sbase + cslot * 16 + 8);
        if (++cslot == NSLOT) { cslot = 0; cph ^= 1; }
    };

    auto epilogue = [&](const float* bias, float* cst, __half* outp, float* h2f) {
        #pragma unroll
        for (int mf = 0; mf < 2; mf++) {
            const int rbase = m0 + wm * 32 + mf * 16 + (lane >> 2) + 8 * (lane & 1);
            #pragma unroll
            for (int nf = 0; nf < 4; nf++) {
                float c0 = acc[mf][nf][0], c1 = acc[mf][nf][1];
                float c2 = acc[mf][nf][2], c3 = acc[mf][nf][3];
                float p0 = __shfl_xor_sync(0xffffffffu, c0, 1);
                float p1 = __shfl_xor_sync(0xffffffffu, c1, 1);
                float p2 = __shfl_xor_sync(0xffffffffu, c2, 1);
                float p3 = __shfl_xor_sync(0xffffffffu, c3, 1);
                float zi, zf, zg, zo;
                if ((lane & 1) == 0) { zi = c0; zf = c1; zg = p0; zo = p1; }
                else                 { zi = p2; zf = p3; zg = c2; zo = c3; }
                const int u = u0 + wn * 8 + nf * 2 + ((lane & 3) >> 1);
                zi += bias[u];
                zf += bias[U_ + u];
                zg += bias[2 * U_ + u];
                zo += bias[3 * U_ + u];
                const size_t gi = (size_t)rbase * U_ + u;
                const float cold = cst[gi];
                const float cn = sigmoidf_(zf) * cold + sigmoidf_(zi) * tanhf_(zg);
                const float hv = sigmoidf_(zo) * tanhf_(cn);
                cst[gi] = cn;
                const uint32_t ho = (uint32_t)(u >> 6) * ACH_E
                                  + (SWZb((uint32_t)rbase * 128 + (uint32_t)(u & 63) * 2) >> 1);
                outp[ho] = __float2half_rn(hv);
                if (h2f) h2f[gi] = hv;
            }
        }
    };

    auto jobA = [&](const JobP& J, int c) -> const __half* {
        return ((c < J.a0n) ? J.a0 + (size_t)c * ACH_E
                            : J.a1 + (size_t)(c - J.a0n) * ACH_E) + (size_t)m0 * 64;
    };

    // run one phase: job0 (+ optional job1), fully pipelined, no CTA barriers
    auto run_phase = [&](const JobP& j0, const float* bias0, float* cst0,
                         __half* out0, float* h2f0,
                         bool two, const JobP& j1, const float* bias1,
                         float* cst1, __half* out1) {
        const int ntot = j0.nch + (two ? j1.nch : 0);
        auto getA = [&](int g) {
            return (g < j0.nch) ? jobA(j0, g) : jobA(j1, g - j0.nch);
        };
        auto getB = [&](int g) {
            const JobP& J = (g < j0.nch) ? j0 : j1;
            const int c = (g < j0.nch) ? g : g - j0.nch;
            return J.Bw + (size_t)c * BCH_E + (size_t)n0 * 64;
        };
        if (tid == 0) {
            const int pre = ntot < LA ? ntot : LA;
            for (int g = 0; g < pre; g++) issue_one(getA(g), getB(g));
        }
        zero_acc();
        for (int g = 0; g < ntot; g++) {
            if (tid == 0 && g + LA < ntot) issue_one(getA(g + LA), getB(g + LA));
            consume_one();
            if (two && g == j0.nch - 1) {
                epilogue(bias0, cst0, out0, h2f0);
                zero_acc();
            }
        }
        if (two) epilogue(bias1, cst1, out1, nullptr);
        else     epilogue(bias0, cst0, out0, h2f0);
    };

    unsigned gen = 0;

    // Phase 0: layer1(0) — x(0) + h1_init(buf0, zeros) -> h1(0) in buf1
    {
        JobP j = {NCH1, 1, g_xf, g_h1, g_B1};
        run_phase(j, b1, g_c1, g_h1 + HS, nullptr, false, j, nullptr, nullptr, nullptr);
    }
    grid_sync(++gen);

    // Fused phases: layer2(t) then layer1(t+1)  (both depend only on synced data)
    for (int t = 0; t < T_ - 1; t++) {
        const int rd1 = (t + 1) & 1;   // buffer holding h1(t)
        const int rd2 = t & 1;         // buffer holding h2(t-1)
        JobP jl2 = {NCH2, 8, g_h1 + (size_t)rd1 * HS, g_h2 + (size_t)rd2 * HS, g_B2};
        JobP jl1 = {NCH1, 1, g_xf + (size_t)(t + 1) * ACH_E, g_h1 + (size_t)rd1 * HS, g_B1};
        run_phase(jl2, b2, g_c2, g_h2 + (size_t)(rd2 ^ 1) * HS, g_h2f,
                  true, jl1, b1, g_c1, g_h1 + (size_t)(rd1 ^ 1) * HS);
        grid_sync(++gen);
    }

    // Final phase: layer2(255)
    {
        const int t = T_ - 1;
        const int rd1 = (t + 1) & 1, rd2 = t & 1;
        JobP jl2 = {NCH2, 8, g_h1 + (size_t)rd1 * HS, g_h2 + (size_t)rd2 * HS, g_B2};
        run_phase(jl2, b2, g_c2, g_h2 + (size_t)(rd2 ^ 1) * HS, g_h2f,
                  false, jl2, nullptr, nullptr, nullptr);
    }
    grid_sync(++gen);

    // Dense head: 2048 warps; first 1024 take one batch row each.
    const int w = blockIdx.x * (NT / 32) + ww;
    if (w < B_) {
        const float* h = g_h2f + (size_t)w * U_;
        float s = 0.f;
        #pragma unroll
        for (int k = lane; k < U_; k += 32) s += h[k] * Wd[k];
        #pragma unroll
        for (int off = 16; off; off >>= 1) s += __shfl_down_sync(0xffffffffu, s, off);
        if (lane == 0) out[w] = s + bd[0];
    }
}

// ---------------- prep kernels (deterministic, run every replay) ------------
// Weights -> [chunk][n'][64] fp16, SW128-swizzled 128B rows.
__global__ void prep_weights(const float* __restrict__ W1, const float* __restrict__ Uh1,
                             const float* __restrict__ W2, const float* __restrict__ Uh2)
{
    const long total1 = (long)NG * K1;
    const long total  = total1 + (long)NG * K2;
    for (long idx = blockIdx.x * (long)blockDim.x + threadIdx.x; idx < total;
         idx += (long)gridDim.x * blockDim.x) {
        if (idx < total1) {
            const int np = (int)(idx / K1), k = (int)(idx % K1);
            const int n = ((np & 3) << 9) | (np >> 2);
            const float v = (k < D_) ? W1[(size_t)k * NG + n] : Uh1[(size_t)(k - D_) * NG + n];
            const long o = (long)(k >> 6) * BCH_E
                         + (SWZb((uint32_t)np * 128 + (uint32_t)(k & 63) * 2) >> 1);
            g_B1[o] = __float2half_rn(v);
        } else {
            const long i2 = idx - total1;
            const int np = (int)(i2 / K2), k = (int)(i2 % K2);
            const int n = ((np & 3) << 9) | (np >> 2);
            const float v = (k < U_) ? W2[(size_t)k * NG + n] : Uh2[(size_t)(k - U_) * NG + n];
            const long o = (long)(k >> 6) * BCH_E
                         + (SWZb((uint32_t)np * 128 + (uint32_t)(k & 63) * 2) >> 1);
            g_B2[o] = __float2half_rn(v);
        }
    }
}

// x -> [t][m][64] fp16, SW128-swizzled rows
__global__ void prep_x(const float* __restrict__ inputs)
{
    const long total = (long)T_ * B_ * D_;
    for (long idx = blockIdx.x * (long)blockDim.x + threadIdx.x; idx < total;
         idx += (long)gridDim.x * blockDim.x) {
        const int k = (int)(idx & 63);
        const int m = (int)((idx >> 6) & 1023);
        const int t = (int)(idx >> 16);
        const float v = inputs[(size_t)m * (T_ * D_) + (size_t)t * D_ + k];
        const long o = (long)t * ACH_E + (SWZb((uint32_t)m * 128 + (uint32_t)k * 2) >> 1);
        g_xf[o] = __float2half_rn(v);
    }
}

__global__ void init_state()
{
    const int i = blockIdx.x * blockDim.x + threadIdx.x;   // HS threads
    const __half z = __float2half_rn(0.f);
    g_h1[i] = z;                     // buffer 0 (zeros; layout-independent)
    g_h2[i] = z;
    g_c1[i] = 0.f; g_c2[i] = 0.f;
    if (i == 0) { g_count = 0; g_gen = 0; }
}

extern "C" void kernel_launch(void* const* d_in, const int* in_sizes, int n_in,
                              void* d_out, int out_size)
{
    const float* inputs = (const float*)d_in[0];
    const float* W1  = (const float*)d_in[1];
    const float* Uh1 = (const float*)d_in[2];
    const float* b1  = (const float*)d_in[3];
    const float* W2  = (const float*)d_in[4];
    const float* Uh2 = (const float*)d_in[5];
    const float* b2  = (const float*)d_in[6];
    const float* Wd  = (const float*)d_in[7];
    const float* bd  = (const float*)d_in[8];
    float* out = (float*)d_out;

    cudaFuncSetAttribute(lstm_persistent,
                         cudaFuncAttributeMaxDynamicSharedMemorySize, SMEM_DYN);

    prep_weights<<<2048, 256>>>(W1, Uh1, W2, Uh2);
    prep_x<<<4096, 256>>>(inputs);
    init_state<<<HS / 256, 256>>>();
    lstm_persistent<<<NBLK, NT, SMEM_DYN>>>(b1, b2, Wd, bd, out);
}